// round 7
// baseline (speedup 1.0000x reference)
#include <cuda_runtime.h>

#define N_COL 256
#define N_ROW 256
#define N_CELLS (N_COL * N_ROW)
#define N_WORDS (N_CELLS / 32)          // 2048 bitmask words
#define N_AGENT_PTS (64 * 1001)         // 64064
#define BATCH 512
#define N_M4 (N_CELLS / 4)              // 16384 float4s per batch row
#define BPT 4                           // batch rows per apply thread

#define GRID_BLOCKS 8192                // N_M4 * (BATCH/BPT) / 256
#define SCAT_BLOCKS 256                 // blocks with scatter duty (all in wave 1)

// Scratch: [0..N_WORDS) bitmask, [N_WORDS] touched-cell counter.
__device__ unsigned int g_state[N_WORDS + 1];
// Monotonic counters — never reset, so graph replays are deterministic.
// Epoch derivation is unambiguous because replays execute sequentially.
__device__ unsigned int g_blk_arrive;   // +GRID_BLOCKS per call
__device__ unsigned int g_zero_done;    // +SCAT_BLOCKS per call
__device__ unsigned int g_scat_done;    // +SCAT_BLOCKS per call

__device__ __forceinline__ unsigned int ld_vol(const unsigned int* p) {
    unsigned int v;
    asm volatile("ld.volatile.global.u32 %0, [%1];" : "=r"(v) : "l"(p));
    return v;
}

__global__ void __launch_bounds__(256)
k_fused(const float* __restrict__ ax, const float* __restrict__ ay,
        const float4* __restrict__ in, float4* __restrict__ out) {
    __shared__ unsigned int s_epoch;
    const int t = threadIdx.x;
    const int b = blockIdx.x;

    if (t == 0) s_epoch = atomicAdd(&g_blk_arrive, 1u) / GRID_BLOCKS;
    __syncthreads();
    const unsigned int epoch = s_epoch;
    const unsigned int target = (epoch + 1u) * SCAT_BLOCKS;

    // ---- scatter duty: blocks 0..255 ----
    if (b < SCAT_BLOCKS) {
        // zero my 8-word slice (+ the counter word)
        if (t < 8) g_state[b * 8 + t] = 0u;
        if (b == 0 && t == 8) g_state[N_WORDS] = 0u;
        __syncthreads();
        if (t == 0) {
            __threadfence();
            atomicAdd(&g_zero_done, 1u);
            while ((int)(ld_vol(&g_zero_done) - target) < 0) __nanosleep(64);
            __threadfence();
        }
        __syncthreads();

        // one agent point per thread (65536 threads >= 64064 points)
        int i = b * 256 + t;
        if (i < N_AGENT_PTS) {
            float fx = ax[i] * (float)N_COL;
            float fy = ay[i] * (float)N_ROW;
            float cx = floorf(fx);
            float cy = floorf(fy);
            float rx = fx - cx;
            float ry = fy - cy;
            bool in_box = (rx >= 0.25f) && (rx <= 0.75f) &&
                          (ry >= 0.25f) && (ry <= 0.75f);
            if (in_box) {
                int ix = min(max((int)cx, 0), N_COL - 1);
                int iy = min(max((int)cy, 0), N_ROW - 1);
                // rot90 CCW folded in: (ix,iy) -> k = (255-iy)*256 + ix
                int k = (N_ROW - 1 - iy) * N_COL + ix;
                unsigned int bit = 1u << (k & 31);
                unsigned int old = atomicOr(&g_state[k >> 5], bit);
                if (!(old & bit)) atomicAdd(&g_state[N_WORDS], 1u);
            }
        }
        __syncthreads();
        if (t == 0) {
            __threadfence();             // publish this block's atomics
            atomicAdd(&g_scat_done, 1u);
        }
    }

    // ---- apply: all 8192 blocks ----
    const int tid = b * 256 + t;
    const int m = tid & (N_M4 - 1);      // float4 index within a batch row
    const int g = tid >> 14;             // batch group (0..127)
    const long base = (long)(g * BPT) * N_M4 + m;
    const float4* p = in + base;
    float4* q = out + base;

    // 4 independent streaming loads — issued BEFORE the spin (cannot sink
    // past the volatile asm), so DRAM stays busy while scatter finishes.
    float4 v0 = __ldcs(p + 0 * N_M4);
    float4 v1 = __ldcs(p + 1 * N_M4);
    float4 v2 = __ldcs(p + 2 * N_M4);
    float4 v3 = __ldcs(p + 3 * N_M4);

    if (t == 0) {
        while ((int)(ld_vol(&g_scat_done) - target) < 0) __nanosleep(64);
        __threadfence();
    }
    __syncthreads();

    // mask reads via L2 (bypass L1 -> no stale-line risk)
    unsigned int cnt = __ldcg(&g_state[N_WORDS]);
    float scale = (float)N_CELLS / (float)(N_CELLS - cnt);
    unsigned int word = __ldcg(&g_state[m >> 3]);
    unsigned int bits = (word >> ((m & 7) * 4)) & 0xFu;

    float sx = (bits & 1u) ? 0.0f : scale;
    float sy = (bits & 2u) ? 0.0f : scale;
    float sz = (bits & 4u) ? 0.0f : scale;
    float sw = (bits & 8u) ? 0.0f : scale;

    v0.x *= sx; v0.y *= sy; v0.z *= sz; v0.w *= sw;
    v1.x *= sx; v1.y *= sy; v1.z *= sz; v1.w *= sw;
    v2.x *= sx; v2.y *= sy; v2.z *= sz; v2.w *= sw;
    v3.x *= sx; v3.y *= sy; v3.z *= sz; v3.w *= sw;

    q[0 * N_M4] = v0;
    q[1 * N_M4] = v1;
    q[2 * N_M4] = v2;
    q[3 * N_M4] = v3;
}

extern "C" void kernel_launch(void* const* d_in, const int* in_sizes, int n_in,
                              void* d_out, int out_size) {
    const float* input = (const float*)d_in[0];
    const float* agents_x = (const float*)d_in[1];
    const float* agents_y = (const float*)d_in[2];
    float* out = (float*)d_out;

    k_fused<<<GRID_BLOCKS, 256>>>(agents_x, agents_y,
                                  (const float4*)input, (float4*)out);
}

// round 8
// speedup vs baseline: 1.0029x; 1.0029x over previous
#include <cuda_runtime.h>

#define N_COL 256
#define N_ROW 256
#define N_CELLS (N_COL * N_ROW)
#define N_AGENT_PTS (64 * 1001)         // 64064
#define BATCH 512
#define N_M4 (N_CELLS / 4)              // 16384 float4s per batch row
#define BPT 4                           // batch rows per apply thread

#define GRID_BLOCKS 8192                // N_M4 * (BATCH/BPT) / 256
#define SCAT_BLOCKS 251                 // ceil(64064/256); all in wave 1

// Epoch-tagged mask cells: cell == tag(epoch) means "touched this call".
// Tags are monotonic and never repeat, so NO zeroing phase is needed.
__device__ __align__(16) unsigned int g_cells[N_CELLS];   // 256 KB, L2-resident
// Per-epoch touched counts, rotating slots. Slot (e+1)&3 is zeroed during
// call e (plain store, visible at the next kernel boundary). Zero-initialized
// at module load, so call 0's slot 0 is valid.
__device__ unsigned int g_cnt[4];
// Monotonic counters — never reset -> graph-replay deterministic.
__device__ unsigned int g_blk_arrive;   // +GRID_BLOCKS per call
__device__ unsigned int g_scat_done;    // +SCAT_BLOCKS per call

__device__ __forceinline__ unsigned int ld_vol(const unsigned int* p) {
    unsigned int v;
    asm volatile("ld.volatile.global.u32 %0, [%1];" : "=r"(v) : "l"(p) : "memory");
    return v;
}

__global__ void __launch_bounds__(256)
k_fused(const float* __restrict__ ax, const float* __restrict__ ay,
        const float4* __restrict__ in, float4* __restrict__ out) {
    __shared__ unsigned int s_epoch;
    __shared__ unsigned int s_cnt;
    const int t = threadIdx.x;
    const int b = blockIdx.x;

    if (t == 0) s_epoch = atomicAdd(&g_blk_arrive, 1u) / GRID_BLOCKS;
    __syncthreads();
    const unsigned int epoch = s_epoch;
    const unsigned int tag = epoch + 1u;                 // never repeats
    const unsigned int target = (epoch + 1u) * SCAT_BLOCKS;

    // ---- apply addressing; issue the 4 independent input loads FIRST ----
    const int tid = b * 256 + t;
    const int m = tid & (N_M4 - 1);      // float4 index within a batch row
    const int g = tid >> 14;             // batch group (0..127)
    const long base = (long)(g * BPT) * N_M4 + m;
    const float4* p = in + base;
    float4* q = out + base;

    float4 v0 = __ldcs(p + 0 * N_M4);
    float4 v1 = __ldcs(p + 1 * N_M4);
    float4 v2 = __ldcs(p + 2 * N_M4);
    float4 v3 = __ldcs(p + 3 * N_M4);

    // ---- scatter duty: blocks 0..250, one point per thread, NO zero phase ----
    if (b < SCAT_BLOCKS) {
        if (b == 0 && t == 1) g_cnt[(epoch + 1u) & 3] = 0u;   // prep next epoch
        int i = b * 256 + t;
        if (i < N_AGENT_PTS) {
            float fx = ax[i] * (float)N_COL;
            float fy = ay[i] * (float)N_ROW;
            float cx = floorf(fx);
            float cy = floorf(fy);
            float rx = fx - cx;
            float ry = fy - cy;
            bool in_box = (rx >= 0.25f) && (rx <= 0.75f) &&
                          (ry >= 0.25f) && (ry <= 0.75f);
            if (in_box) {
                int ix = min(max((int)cx, 0), N_COL - 1);
                int iy = min(max((int)cy, 0), N_ROW - 1);
                // rot90 CCW folded in: (ix,iy) -> k = (255-iy)*256 + ix
                int k = (N_ROW - 1 - iy) * N_COL + ix;
                unsigned int old = atomicExch(&g_cells[k], tag);
                if (old != tag)                      // first toucher this epoch
                    atomicAdd(&g_cnt[epoch & 3], 1u);
            }
        }
        __syncthreads();
        if (t == 0) {
            __threadfence();                         // publish block's atomics
            atomicAdd(&g_scat_done, 1u);
        }
    }

    // ---- wait for scatter completion (loads above are already in flight) ----
    if (t == 0) {
        while ((int)(ld_vol(&g_scat_done) - target) < 0) __nanosleep(32);
        __threadfence();
        s_cnt = __ldcg(&g_cnt[epoch & 3]);
    }
    __syncthreads();

    const float scale = (float)N_CELLS / (float)(N_CELLS - s_cnt);

    // 4 consecutive cells for this m, one 16B L2 read
    uint4 cw = __ldcg(reinterpret_cast<const uint4*>(g_cells) + m);
    float sx = (cw.x == tag) ? 0.0f : scale;
    float sy = (cw.y == tag) ? 0.0f : scale;
    float sz = (cw.z == tag) ? 0.0f : scale;
    float sw = (cw.w == tag) ? 0.0f : scale;

    v0.x *= sx; v0.y *= sy; v0.z *= sz; v0.w *= sw;
    v1.x *= sx; v1.y *= sy; v1.z *= sz; v1.w *= sw;
    v2.x *= sx; v2.y *= sy; v2.z *= sz; v2.w *= sw;
    v3.x *= sx; v3.y *= sy; v3.z *= sz; v3.w *= sw;

    q[0 * N_M4] = v0;
    q[1 * N_M4] = v1;
    q[2 * N_M4] = v2;
    q[3 * N_M4] = v3;
}

extern "C" void kernel_launch(void* const* d_in, const int* in_sizes, int n_in,
                              void* d_out, int out_size) {
    const float* input = (const float*)d_in[0];
    const float* agents_x = (const float*)d_in[1];
    const float* agents_y = (const float*)d_in[2];
    float* out = (float*)d_out;

    k_fused<<<GRID_BLOCKS, 256>>>(agents_x, agents_y,
                                  (const float4*)input, (float4*)out);
}

// round 9
// speedup vs baseline: 1.0367x; 1.0337x over previous
#include <cuda_runtime.h>

#define N_COL 256
#define N_ROW 256
#define N_CELLS (N_COL * N_ROW)
#define N_AGENT_PTS (64 * 1001)         // 64064
#define BATCH 512
#define N_M4 (N_CELLS / 4)              // 16384 float4s per batch row
#define BPT 8                           // batch rows per apply thread
#define N_GROUPS (BATCH / BPT)          // 64

#define GRID_BLOCKS (N_M4 * N_GROUPS / 256)   // 4096
#define SCAT_BLOCKS 251                 // ceil(64064/256); all in wave 1

// Epoch-tagged mask cells: cell == tag(epoch) means "touched this call".
// Tags are monotonic and never repeat -> NO zeroing phase needed.
__device__ __align__(16) unsigned int g_cells[N_CELLS];   // 256 KB, L2-resident
// Per-epoch touched counts, rotating slots (next slot zeroed during this call).
__device__ unsigned int g_cnt[4];
// Monotonic counters — never reset -> graph-replay deterministic.
__device__ unsigned int g_blk_arrive;   // +GRID_BLOCKS per call
__device__ unsigned int g_scat_done;    // +SCAT_BLOCKS per call

__device__ __forceinline__ unsigned int ld_vol(const unsigned int* p) {
    unsigned int v;
    asm volatile("ld.volatile.global.u32 %0, [%1];" : "=r"(v) : "l"(p) : "memory");
    return v;
}

__global__ void __launch_bounds__(256)
k_fused(const float* __restrict__ ax, const float* __restrict__ ay,
        const float4* __restrict__ in, float4* __restrict__ out) {
    __shared__ unsigned int s_epoch;
    __shared__ unsigned int s_cnt;
    const int t = threadIdx.x;
    const int b = blockIdx.x;

    if (t == 0) s_epoch = atomicAdd(&g_blk_arrive, 1u) / GRID_BLOCKS;
    __syncthreads();
    const unsigned int epoch = s_epoch;
    const unsigned int tag = epoch + 1u;                 // never repeats
    const unsigned int target = (epoch + 1u) * SCAT_BLOCKS;

    // ---- scatter duty FIRST in blocks 0..250 (queue priority for agent loads)
    if (b < SCAT_BLOCKS) {
        if (b == 0 && t == 1) g_cnt[(epoch + 1u) & 3] = 0u;   // prep next epoch
        const int i = b * 256 + t;
        bool first = false;
        if (i < N_AGENT_PTS) {
            float fx = ax[i] * (float)N_COL;
            float fy = ay[i] * (float)N_ROW;
            float cx = floorf(fx);
            float cy = floorf(fy);
            float rx = fx - cx;
            float ry = fy - cy;
            bool in_box = (rx >= 0.25f) && (rx <= 0.75f) &&
                          (ry >= 0.25f) && (ry <= 0.75f);
            if (in_box) {
                int ix = min(max((int)cx, 0), N_COL - 1);
                int iy = min(max((int)cy, 0), N_ROW - 1);
                // rot90 CCW folded in: (ix,iy) -> k = (255-iy)*256 + ix
                int k = (N_ROW - 1 - iy) * N_COL + ix;
                unsigned int old = atomicExch(&g_cells[k], tag);
                first = (old != tag);                // first toucher this epoch
            }
        }
        // warp-aggregated count: one atomic per warp
        unsigned int ball = __ballot_sync(0xffffffffu, first);
        if ((t & 31) == 0 && ball)
            atomicAdd(&g_cnt[epoch & 3], __popc(ball));
        __syncthreads();
        if (t == 0) {
            __threadfence();                         // publish block's atomics
            atomicAdd(&g_scat_done, 1u);
        }
    }

    // ---- apply addressing; 8 independent input loads (128 B/thread in flight)
    const int tid = b * 256 + t;
    const int m = tid & (N_M4 - 1);      // float4 index within a batch row
    const int g = tid >> 14;             // batch group (0..63)
    const long base = (long)(g * BPT) * N_M4 + m;
    const float4* p = in + base;
    float4* q = out + base;

    float4 v0 = __ldcs(p + 0 * N_M4);
    float4 v1 = __ldcs(p + 1 * N_M4);
    float4 v2 = __ldcs(p + 2 * N_M4);
    float4 v3 = __ldcs(p + 3 * N_M4);
    float4 v4 = __ldcs(p + 4 * N_M4);
    float4 v5 = __ldcs(p + 5 * N_M4);
    float4 v6 = __ldcs(p + 6 * N_M4);
    float4 v7 = __ldcs(p + 7 * N_M4);

    // ---- wait for scatter completion (loads above already in flight) ----
    if (t == 0) {
        while ((int)(ld_vol(&g_scat_done) - target) < 0) __nanosleep(32);
        __threadfence();
        s_cnt = __ldcg(&g_cnt[epoch & 3]);
    }
    __syncthreads();

    const float scale = (float)N_CELLS / (float)(N_CELLS - s_cnt);

    // 4 consecutive cells for this m, one 16B L2 read
    uint4 cw = __ldcg(reinterpret_cast<const uint4*>(g_cells) + m);
    float sx = (cw.x == tag) ? 0.0f : scale;
    float sy = (cw.y == tag) ? 0.0f : scale;
    float sz = (cw.z == tag) ? 0.0f : scale;
    float sw = (cw.w == tag) ? 0.0f : scale;

    v0.x *= sx; v0.y *= sy; v0.z *= sz; v0.w *= sw;
    v1.x *= sx; v1.y *= sy; v1.z *= sz; v1.w *= sw;
    v2.x *= sx; v2.y *= sy; v2.z *= sz; v2.w *= sw;
    v3.x *= sx; v3.y *= sy; v3.z *= sz; v3.w *= sw;
    v4.x *= sx; v4.y *= sy; v4.z *= sz; v4.w *= sw;
    v5.x *= sx; v5.y *= sy; v5.z *= sz; v5.w *= sw;
    v6.x *= sx; v6.y *= sy; v6.z *= sz; v6.w *= sw;
    v7.x *= sx; v7.y *= sy; v7.z *= sz; v7.w *= sw;

    q[0 * N_M4] = v0;
    q[1 * N_M4] = v1;
    q[2 * N_M4] = v2;
    q[3 * N_M4] = v3;
    q[4 * N_M4] = v4;
    q[5 * N_M4] = v5;
    q[6 * N_M4] = v6;
    q[7 * N_M4] = v7;
}

extern "C" void kernel_launch(void* const* d_in, const int* in_sizes, int n_in,
                              void* d_out, int out_size) {
    const float* input = (const float*)d_in[0];
    const float* agents_x = (const float*)d_in[1];
    const float* agents_y = (const float*)d_in[2];
    float* out = (float*)d_out;

    k_fused<<<GRID_BLOCKS, 256>>>(agents_x, agents_y,
                                  (const float4*)input, (float4*)out);
}

// round 10
// speedup vs baseline: 1.1151x; 1.0756x over previous
#include <cuda_runtime.h>

#define N_COL 256
#define N_ROW 256
#define N_CELLS (N_COL * N_ROW)
#define N_AGENT_PTS (64 * 1001)         // 64064
#define BATCH 512
#define N_M4 (N_CELLS / 4)              // 16384 float4s per batch row
#define BPT 4                           // batch rows per apply thread

#define SCAT_BLOCKS 251                 // ceil(64064/256)
#define APPLY_BLOCKS (N_M4 * (BATCH / BPT) / 256)   // 8192

// Epoch-tagged mask cells: cell == tag(epoch) <=> touched this call.
// Tags are monotonic and never repeat -> no zeroing, no barrier, ever.
__device__ __align__(16) unsigned int g_cells[N_CELLS];   // 256 KB, L2-resident
// Per-epoch touched counts, 4 rotating slots. Slot (e+1)&3 is zeroed during
// call e; the kernel boundary publishes it before call e+1 reads it.
// Zero-initialized at load, so epoch 0's slot 0 is valid.
__device__ unsigned int g_cnt[4];
// Monotonic per-kernel call counters (never reset -> replay-deterministic).
// Each kernel runs exactly once per kernel_launch, so the two epochs agree.
__device__ unsigned int g_scat_calls;
__device__ unsigned int g_apply_calls;

// Scatter: 251 blocks, one agent point per thread. No init, no rendezvous.
__global__ void __launch_bounds__(256)
k_scatter(const float* __restrict__ ax, const float* __restrict__ ay) {
    __shared__ unsigned int s_epoch;
    const int t = threadIdx.x;
    if (t == 0) s_epoch = atomicAdd(&g_scat_calls, 1u) / SCAT_BLOCKS;
    __syncthreads();
    const unsigned int epoch = s_epoch;
    const unsigned int tag = epoch + 1u;               // never repeats

    if (blockIdx.x == 0 && t == 1) g_cnt[(epoch + 1u) & 3] = 0u;  // prep next

    const int i = blockIdx.x * 256 + t;
    bool first = false;
    if (i < N_AGENT_PTS) {
        float fx = ax[i] * (float)N_COL;
        float fy = ay[i] * (float)N_ROW;
        float cx = floorf(fx);
        float cy = floorf(fy);
        float rx = fx - cx;
        float ry = fy - cy;
        bool in_box = (rx >= 0.25f) && (rx <= 0.75f) &&
                      (ry >= 0.25f) && (ry <= 0.75f);
        if (in_box) {
            int ix = min(max((int)cx, 0), N_COL - 1);
            int iy = min(max((int)cy, 0), N_ROW - 1);
            // rot90 CCW folded in: (ix,iy) -> k = (255-iy)*256 + ix
            int k = (N_ROW - 1 - iy) * N_COL + ix;
            unsigned int old = atomicExch(&g_cells[k], tag);
            first = (old != tag);                      // first toucher this epoch
        }
    }
    // warp-aggregated count: one atomic per warp with any first-touch
    unsigned int ball = __ballot_sync(0xffffffffu, first);
    if ((t & 31) == 0 && ball)
        atomicAdd(&g_cnt[epoch & 3], __popc(ball));
}

// Apply: out = in * mask * scale. Best-measured shape (BPT=4, MLP=4).
__global__ void __launch_bounds__(256)
k_apply(const float4* __restrict__ in, float4* __restrict__ out) {
    __shared__ unsigned int s_epoch;
    const int t = threadIdx.x;
    if (t == 0) s_epoch = atomicAdd(&g_apply_calls, 1u) / APPLY_BLOCKS;
    __syncthreads();
    const unsigned int epoch = s_epoch;
    const unsigned int tag = epoch + 1u;

    const int tid = blockIdx.x * 256 + t;
    const int m = tid & (N_M4 - 1);      // float4 index within a batch row
    const int g = tid >> 14;             // batch group (0..127)
    const long base = (long)(g * BPT) * N_M4 + m;
    const float4* p = in + base;
    float4* q = out + base;

    // 4 independent read-once streaming loads (MLP=4)
    float4 v0 = __ldcs(p + 0 * N_M4);
    float4 v1 = __ldcs(p + 1 * N_M4);
    float4 v2 = __ldcs(p + 2 * N_M4);
    float4 v3 = __ldcs(p + 3 * N_M4);

    unsigned int cnt = g_cnt[epoch & 3];
    float scale = (float)N_CELLS / (float)(N_CELLS - cnt);

    // 4 consecutive cells for this m, one 16B read (L2-resident)
    uint4 cw = reinterpret_cast<const uint4*>(g_cells)[m];
    float sx = (cw.x == tag) ? 0.0f : scale;
    float sy = (cw.y == tag) ? 0.0f : scale;
    float sz = (cw.z == tag) ? 0.0f : scale;
    float sw = (cw.w == tag) ? 0.0f : scale;

    v0.x *= sx; v0.y *= sy; v0.z *= sz; v0.w *= sw;
    v1.x *= sx; v1.y *= sy; v1.z *= sz; v1.w *= sw;
    v2.x *= sx; v2.y *= sy; v2.z *= sz; v2.w *= sw;
    v3.x *= sx; v3.y *= sy; v3.z *= sz; v3.w *= sw;

    q[0 * N_M4] = v0;
    q[1 * N_M4] = v1;
    q[2 * N_M4] = v2;
    q[3 * N_M4] = v3;
}

extern "C" void kernel_launch(void* const* d_in, const int* in_sizes, int n_in,
                              void* d_out, int out_size) {
    const float* input = (const float*)d_in[0];
    const float* agents_x = (const float*)d_in[1];
    const float* agents_y = (const float*)d_in[2];
    float* out = (float*)d_out;

    k_scatter<<<SCAT_BLOCKS, 256>>>(agents_x, agents_y);
    k_apply<<<APPLY_BLOCKS, 256>>>((const float4*)input, (float4*)out);
}

// round 11
// speedup vs baseline: 1.1158x; 1.0006x over previous
#include <cuda_runtime.h>
#include <cuda_device_runtime_api.h>

#define N_COL 256
#define N_ROW 256
#define N_CELLS (N_COL * N_ROW)
#define N_AGENT_PTS (64 * 1001)         // 64064
#define BATCH 512
#define N_M4 (N_CELLS / 4)              // 16384 float4s per batch row
#define BPT 4                           // batch rows per apply thread

#define SCAT_BLOCKS 251                 // ceil(64064/256)
#define APPLY_BLOCKS (N_M4 * (BATCH / BPT) / 256)   // 8192

// Epoch-tagged mask cells: cell == tag(epoch) <=> touched this call.
// Tags are monotonic and never repeat -> no zeroing, no barrier, ever.
__device__ __align__(16) unsigned int g_cells[N_CELLS];   // 256 KB, L2-resident
// Per-epoch touched counts, 4 rotating slots (slot (e+1)&3 zeroed in call e).
__device__ unsigned int g_cnt[4];
// Published tag for the current call (written by scatter, read by apply —
// ordered by the grid dependency / kernel boundary).
__device__ unsigned int g_tag_pub;
// Monotonic scatter call counter (never reset -> replay-deterministic).
__device__ unsigned int g_scat_calls;

// Scatter: 251 blocks, one agent point per thread. No init, no rendezvous.
__global__ void __launch_bounds__(256)
k_scatter(const float* __restrict__ ax, const float* __restrict__ ay) {
    cudaTriggerProgrammaticLaunchCompletion();

    __shared__ unsigned int s_epoch;
    const int t = threadIdx.x;
    if (t == 0) s_epoch = atomicAdd(&g_scat_calls, 1u) / SCAT_BLOCKS;
    __syncthreads();
    const unsigned int epoch = s_epoch;
    const unsigned int tag = epoch + 1u;               // never repeats

    if (blockIdx.x == 0) {
        if (t == 1) g_cnt[(epoch + 1u) & 3] = 0u;      // prep next epoch's slot
        if (t == 2) g_tag_pub = tag;                   // publish tag for apply
    }

    const int i = blockIdx.x * 256 + t;
    bool first = false;
    if (i < N_AGENT_PTS) {
        float fx = ax[i] * (float)N_COL;
        float fy = ay[i] * (float)N_ROW;
        float cx = floorf(fx);
        float cy = floorf(fy);
        float rx = fx - cx;
        float ry = fy - cy;
        bool in_box = (rx >= 0.25f) && (rx <= 0.75f) &&
                      (ry >= 0.25f) && (ry <= 0.75f);
        if (in_box) {
            int ix = min(max((int)cx, 0), N_COL - 1);
            int iy = min(max((int)cy, 0), N_ROW - 1);
            // rot90 CCW folded in: (ix,iy) -> k = (255-iy)*256 + ix
            int k = (N_ROW - 1 - iy) * N_COL + ix;
            unsigned int old = atomicExch(&g_cells[k], tag);
            first = (old != tag);                      // first toucher this epoch
        }
    }
    // warp-aggregated count: one atomic per warp with any first-touch
    unsigned int ball = __ballot_sync(0xffffffffu, first);
    if ((t & 31) == 0 && ball)
        atomicAdd(&g_cnt[epoch & 3], __popc(ball));
}

// Apply: no atomics, no syncthreads — data loads issue immediately; mask
// state is read only after the grid dependency on scatter resolves.
__global__ void __launch_bounds__(256)
k_apply(const float4* __restrict__ in, float4* __restrict__ out) {
    const int tid = blockIdx.x * 256 + threadIdx.x;
    const int m = tid & (N_M4 - 1);      // float4 index within a batch row
    const int g = tid >> 14;             // batch group (0..127)
    const long base = (long)(g * BPT) * N_M4 + m;
    const float4* p = in + base;
    float4* q = out + base;

    // 4 independent read-once streaming loads, in flight before the sync
    float4 v0 = __ldcs(p + 0 * N_M4);
    float4 v1 = __ldcs(p + 1 * N_M4);
    float4 v2 = __ldcs(p + 2 * N_M4);
    float4 v3 = __ldcs(p + 3 * N_M4);

    // wait for scatter's writes (PDL grid dependency)
    cudaGridDependencySynchronize();

    const unsigned int tag = __ldcg(&g_tag_pub);
    const unsigned int cnt = __ldcg(&g_cnt[(tag - 1u) & 3]);
    const float scale = (float)N_CELLS / (float)(N_CELLS - cnt);

    // 4 consecutive cells for this m, one 16B L2 read
    uint4 cw = __ldcg(reinterpret_cast<const uint4*>(g_cells) + m);
    float sx = (cw.x == tag) ? 0.0f : scale;
    float sy = (cw.y == tag) ? 0.0f : scale;
    float sz = (cw.z == tag) ? 0.0f : scale;
    float sw = (cw.w == tag) ? 0.0f : scale;

    v0.x *= sx; v0.y *= sy; v0.z *= sz; v0.w *= sw;
    v1.x *= sx; v1.y *= sy; v1.z *= sz; v1.w *= sw;
    v2.x *= sx; v2.y *= sy; v2.z *= sz; v2.w *= sw;
    v3.x *= sx; v3.y *= sy; v3.z *= sz; v3.w *= sw;

    q[0 * N_M4] = v0;
    q[1 * N_M4] = v1;
    q[2 * N_M4] = v2;
    q[3 * N_M4] = v3;
}

extern "C" void kernel_launch(void* const* d_in, const int* in_sizes, int n_in,
                              void* d_out, int out_size) {
    const float* input = (const float*)d_in[0];
    const float* agents_x = (const float*)d_in[1];
    const float* agents_y = (const float*)d_in[2];
    float* out = (float*)d_out;

    // Primary: barrier-free epoch scatter
    k_scatter<<<SCAT_BLOCKS, 256>>>(agents_x, agents_y);

    // Secondary: apply with programmatic dependent launch (overlaps scatter)
    cudaLaunchConfig_t cfg = {};
    cfg.gridDim = dim3(APPLY_BLOCKS);
    cfg.blockDim = dim3(256);
    cfg.dynamicSmemBytes = 0;
    cfg.stream = 0;
    cudaLaunchAttribute attrs[1];
    attrs[0].id = cudaLaunchAttributeProgrammaticStreamSerialization;
    attrs[0].val.programmaticStreamSerializationAllowed = 1;
    cfg.attrs = attrs;
    cfg.numAttrs = 1;
    cudaLaunchKernelEx(&cfg, k_apply, (const float4*)input, (float4*)out);
}

// round 12
// speedup vs baseline: 1.1223x; 1.0059x over previous
#include <cuda_runtime.h>

#define N_COL 256
#define N_ROW 256
#define N_CELLS (N_COL * N_ROW)
#define N_WORDS (N_CELLS / 32)          // 2048 bitmask words (8 KB)
#define N_AGENT_PTS (64 * 1001)         // 64064
#define BATCH 512
#define N_M4 (N_CELLS / 4)              // 16384 float4s per batch row
#define BPT 4                           // batch rows per apply thread

#define SCAT_BLOCKS 251                 // ceil(64064/256)
#define APPLY_BLOCKS (N_M4 * (BATCH / BPT) / 256)   // 8192

// Parity double-buffered bitmask + counts. Call with epoch e uses buffer
// e&1, which was zeroed during call e-1's apply kernel (kernel boundary
// publishes the zeroing). Zero-initialized at module load -> epoch 0 valid.
__device__ __align__(16) unsigned int g_mask[2][N_WORDS];
__device__ unsigned int g_cnt[2];
__device__ unsigned int g_par_pub;      // parity of the current call
// Monotonic scatter call counter (never reset -> graph-replay deterministic).
__device__ unsigned int g_scat_calls;

// Scatter: 251 blocks, one agent point per thread.
// No init phase, no barrier — buffer pre-zeroed by previous apply.
__global__ void __launch_bounds__(256)
k_scatter(const float* __restrict__ ax, const float* __restrict__ ay) {
    __shared__ unsigned int s_epoch;
    const int t = threadIdx.x;
    if (t == 0) s_epoch = atomicAdd(&g_scat_calls, 1u) / SCAT_BLOCKS;
    __syncthreads();
    const unsigned int par = s_epoch & 1u;

    if (blockIdx.x == 0 && t == 1) g_par_pub = par;   // publish for apply

    const int i = blockIdx.x * 256 + t;
    bool first = false;
    if (i < N_AGENT_PTS) {
        float fx = ax[i] * (float)N_COL;
        float fy = ay[i] * (float)N_ROW;
        float cx = floorf(fx);
        float cy = floorf(fy);
        float rx = fx - cx;
        float ry = fy - cy;
        bool in_box = (rx >= 0.25f) && (rx <= 0.75f) &&
                      (ry >= 0.25f) && (ry <= 0.75f);
        if (in_box) {
            int ix = min(max((int)cx, 0), N_COL - 1);
            int iy = min(max((int)cy, 0), N_ROW - 1);
            // rot90 CCW folded in: (ix,iy) -> k = (255-iy)*256 + ix
            int k = (N_ROW - 1 - iy) * N_COL + ix;
            unsigned int bit = 1u << (k & 31);
            unsigned int old = atomicOr(&g_mask[par][k >> 5], bit);
            first = !(old & bit);                     // first toucher this call
        }
    }
    // warp-aggregated count: one atomic per warp with any first-touch
    unsigned int ball = __ballot_sync(0xffffffffu, first);
    if ((t & 31) == 0 && ball)
        atomicAdd(&g_cnt[par], __popc(ball));
}

// Apply: out = in * mask * scale — R6's best-measured shape.
// Plain (L1-cached) mask reads are safe: L1 is flushed at launch boundary.
// Side duty: zero the OTHER parity's buffer for the next call (1 store for
// the first 2048 threads — free inside a 37us kernel).
__global__ void __launch_bounds__(256)
k_apply(const float4* __restrict__ in, float4* __restrict__ out) {
    const int t = threadIdx.x;
    const int b = blockIdx.x;
    const int tid = b * 256 + t;

    const unsigned int par = g_par_pub;               // set by this call's scatter

    // zero next call's buffer + count slot
    if (b < 8) g_mask[1u - par][b * 256 + t] = 0u;
    if (b == 8 && t == 0) g_cnt[1u - par] = 0u;

    const int m = tid & (N_M4 - 1);      // float4 index within a batch row
    const int g = tid >> 14;             // batch group (0..127)
    const long base = (long)(g * BPT) * N_M4 + m;
    const float4* p = in + base;
    float4* q = out + base;

    // 4 independent read-once streaming loads (MLP=4)
    float4 v0 = __ldcs(p + 0 * N_M4);
    float4 v1 = __ldcs(p + 1 * N_M4);
    float4 v2 = __ldcs(p + 2 * N_M4);
    float4 v3 = __ldcs(p + 3 * N_M4);

    unsigned int cnt = g_cnt[par];
    float scale = (float)N_CELLS / (float)(N_CELLS - cnt);

    unsigned int word = g_mask[par][m >> 3];          // 4B, L1-resident
    unsigned int bits = (word >> ((m & 7) * 4)) & 0xFu;

    float sx = (bits & 1u) ? 0.0f : scale;
    float sy = (bits & 2u) ? 0.0f : scale;
    float sz = (bits & 4u) ? 0.0f : scale;
    float sw = (bits & 8u) ? 0.0f : scale;

    v0.x *= sx; v0.y *= sy; v0.z *= sz; v0.w *= sw;
    v1.x *= sx; v1.y *= sy; v1.z *= sz; v1.w *= sw;
    v2.x *= sx; v2.y *= sy; v2.z *= sz; v2.w *= sw;
    v3.x *= sx; v3.y *= sy; v3.z *= sz; v3.w *= sw;

    q[0 * N_M4] = v0;
    q[1 * N_M4] = v1;
    q[2 * N_M4] = v2;
    q[3 * N_M4] = v3;
}

extern "C" void kernel_launch(void* const* d_in, const int* in_sizes, int n_in,
                              void* d_out, int out_size) {
    const float* input = (const float*)d_in[0];
    const float* agents_x = (const float*)d_in[1];
    const float* agents_y = (const float*)d_in[2];
    float* out = (float*)d_out;

    k_scatter<<<SCAT_BLOCKS, 256>>>(agents_x, agents_y);
    k_apply<<<APPLY_BLOCKS, 256>>>((const float4*)input, (float4*)out);
}

// round 13
// speedup vs baseline: 1.1601x; 1.0336x over previous
#include <cuda_runtime.h>

#define N_COL 256
#define N_ROW 256
#define N_CELLS (N_COL * N_ROW)
#define N_WORDS (N_CELLS / 32)          // 2048 bitmask words (8 KB)
#define N_AGENT_PTS (64 * 1001)         // 64064
#define N_PTS4 (N_AGENT_PTS / 4)        // 16016
#define BATCH 512
#define N_M4 (N_CELLS / 4)              // 16384 float4s per batch row
#define BPT 4                           // batch rows per apply thread

#define SCAT_BLOCKS 63                  // ceil(16016/256)
#define APPLY_BLOCKS (N_M4 * (BATCH / BPT) / 256)   // 8192

// Parity double-buffered bitmask + counts. Call with epoch e uses buffer
// e&1, zeroed during call e-1's apply (kernel boundary publishes it).
// Zero-initialized at module load -> epoch 0 valid.
__device__ __align__(16) unsigned int g_mask[2][N_WORDS];
__device__ unsigned int g_cnt[2];
__device__ unsigned int g_par_pub;      // parity of the current call
// Monotonic scatter call counter (never reset -> graph-replay deterministic).
__device__ unsigned int g_scat_calls;

__device__ __forceinline__ bool mark_point(float x, float y,
                                           unsigned int par, unsigned int tagbit_unused) {
    float fx = x * (float)N_COL;
    float fy = y * (float)N_ROW;
    float cx = floorf(fx);
    float cy = floorf(fy);
    float rx = fx - cx;
    float ry = fy - cy;
    bool in_box = (rx >= 0.25f) && (rx <= 0.75f) &&
                  (ry >= 0.25f) && (ry <= 0.75f);
    if (!in_box) return false;
    int ix = min(max((int)cx, 0), N_COL - 1);
    int iy = min(max((int)cy, 0), N_ROW - 1);
    // rot90 CCW folded in: (ix,iy) -> k = (255-iy)*256 + ix
    int k = (N_ROW - 1 - iy) * N_COL + ix;
    unsigned int bit = 1u << (k & 31);
    unsigned int old = atomicOr(&g_mask[par][k >> 5], bit);
    return !(old & bit);                // first toucher this call
}

// Scatter: 63 blocks, 4 agent points per thread via float4 loads.
// No init phase, no barrier — buffer pre-zeroed by previous apply.
__global__ void __launch_bounds__(256)
k_scatter(const float4* __restrict__ ax4, const float4* __restrict__ ay4) {
    __shared__ unsigned int s_epoch;
    const int t = threadIdx.x;
    if (t == 0) s_epoch = atomicAdd(&g_scat_calls, 1u) / SCAT_BLOCKS;
    __syncthreads();
    const unsigned int par = s_epoch & 1u;

    if (blockIdx.x == 0 && t == 1) g_par_pub = par;   // publish for apply

    const int j = blockIdx.x * 256 + t;
    int nfirst = 0;
    if (j < N_PTS4) {
        float4 x = ax4[j];
        float4 y = ay4[j];
        nfirst += mark_point(x.x, y.x, par, 0) ? 1 : 0;
        nfirst += mark_point(x.y, y.y, par, 0) ? 1 : 0;
        nfirst += mark_point(x.z, y.z, par, 0) ? 1 : 0;
        nfirst += mark_point(x.w, y.w, par, 0) ? 1 : 0;
    }
    // warp-aggregated count: one atomic per warp
    #pragma unroll
    for (int o = 16; o > 0; o >>= 1)
        nfirst += __shfl_down_sync(0xffffffffu, nfirst, o);
    if ((t & 31) == 0 && nfirst)
        atomicAdd(&g_cnt[par], (unsigned int)nfirst);
}

// Apply: out = in * mask * scale — best-measured shape (BPT=4, MLP=4),
// now with streaming stores. Plain L1-cached mask reads are safe (L1 is
// flushed at launch boundary). Side duty: zero the OTHER parity's buffer.
__global__ void __launch_bounds__(256)
k_apply(const float4* __restrict__ in, float4* __restrict__ out) {
    const int t = threadIdx.x;
    const int b = blockIdx.x;
    const int tid = b * 256 + t;

    const unsigned int par = g_par_pub;               // set by this call's scatter

    // zero next call's buffer + count slot
    if (b < 8) g_mask[1u - par][b * 256 + t] = 0u;
    if (b == 8 && t == 0) g_cnt[1u - par] = 0u;

    const int m = tid & (N_M4 - 1);      // float4 index within a batch row
    const int g = tid >> 14;             // batch group (0..127)
    const long base = (long)(g * BPT) * N_M4 + m;
    const float4* p = in + base;
    float4* q = out + base;

    // 4 independent read-once streaming loads (MLP=4)
    float4 v0 = __ldcs(p + 0 * N_M4);
    float4 v1 = __ldcs(p + 1 * N_M4);
    float4 v2 = __ldcs(p + 2 * N_M4);
    float4 v3 = __ldcs(p + 3 * N_M4);

    unsigned int cnt = g_cnt[par];
    float scale = (float)N_CELLS / (float)(N_CELLS - cnt);

    unsigned int word = g_mask[par][m >> 3];          // 4B, L1-resident
    unsigned int bits = (word >> ((m & 7) * 4)) & 0xFu;

    float sx = (bits & 1u) ? 0.0f : scale;
    float sy = (bits & 2u) ? 0.0f : scale;
    float sz = (bits & 4u) ? 0.0f : scale;
    float sw = (bits & 8u) ? 0.0f : scale;

    v0.x *= sx; v0.y *= sy; v0.z *= sz; v0.w *= sw;
    v1.x *= sx; v1.y *= sy; v1.z *= sz; v1.w *= sw;
    v2.x *= sx; v2.y *= sy; v2.z *= sz; v2.w *= sw;
    v3.x *= sx; v3.y *= sy; v3.z *= sz; v3.w *= sw;

    // streaming stores: evict-first, drain to DRAM early
    __stcs(q + 0 * N_M4, v0);
    __stcs(q + 1 * N_M4, v1);
    __stcs(q + 2 * N_M4, v2);
    __stcs(q + 3 * N_M4, v3);
}

extern "C" void kernel_launch(void* const* d_in, const int* in_sizes, int n_in,
                              void* d_out, int out_size) {
    const float* input = (const float*)d_in[0];
    const float* agents_x = (const float*)d_in[1];
    const float* agents_y = (const float*)d_in[2];
    float* out = (float*)d_out;

    k_scatter<<<SCAT_BLOCKS, 256>>>((const float4*)agents_x,
                                    (const float4*)agents_y);
    k_apply<<<APPLY_BLOCKS, 256>>>((const float4*)input, (float4*)out);
}